// round 4
// baseline (speedup 1.0000x reference)
#include <cuda_runtime.h>

// BaseTextureDiffusion: out[b,c,h,w] = sum_{k=0..48} weights[b,c,k,h,w] *
//                       latent_edgepadded[b,c, h+k/7-3, w+k%7-3]
// Shapes: latent (2,24,256,256) f32, weights (2,24,49,256,256) f32, R=7.
//
// HBM-bound on the 616MB read-once weights stream.
// R4 vs R2 (96.7us): revert persistent grid (R3 regression — tile-boundary
// sync bubbles). 8-row tiles: each 256-thread block stages a 14x264 latent
// tile once and each thread computes TWO output rows sequentially
// (y and y+4). Cuts latent halo refetch 2.5x -> 1.75x and halves block count.
// Keeps __ldcs streaming weights, __stcs output, 7-deep weights MLP.

#define BB 2
#define CC 24
#define HH 256
#define WW 256
#define RR 7
#define PAD 3
#define HW (HH * WW)

#define TILE_ROWS 8                   // output rows per block
#define SROWS (TILE_ROWS + 2 * PAD)   // 14
#define SCOLS 264                     // latent cols -4..259

__global__ __launch_bounds__(256, 6)
void texdiff_kernel(const float* __restrict__ latent,
                    const float* __restrict__ weights,
                    float* __restrict__ out)
{
    __shared__ float tile[SROWS][SCOLS];

    const int bc = blockIdx.z;                 // 0..47  (b*C + c)
    const int h0 = blockIdx.y * TILE_ROWS;     // first output row of tile
    const int x  = threadIdx.x;                // 0..63 : float4 lane over w
    const int y  = threadIdx.y;                // 0..3  : row within half-tile
    const int tid = y * 64 + x;                // 0..255
    const int w0  = 4 * x;

    const float* lat = latent + (long)bc * HW;

    // Stage latent tile with edge clamp:
    // tile[r][cix] = latent[clamp(h0 + r - 3), clamp(cix - 4)]
    #pragma unroll
    for (int idx = tid; idx < SROWS * SCOLS; idx += 256) {
        int r   = idx / SCOLS;
        int cix = idx - r * SCOLS;
        int gh  = h0 + r - PAD;
        gh = gh < 0 ? 0 : (gh > HH - 1 ? HH - 1 : gh);
        int gw  = cix - 4;
        gw = gw < 0 ? 0 : (gw > WW - 1 ? WW - 1 : gw);
        tile[r][cix] = lat[gh * WW + gw];
    }
    __syncthreads();

    // Two sequential passes: output rows h0+y and h0+y+4.
    #pragma unroll
    for (int rr = 0; rr < 2; rr++) {
        const int yy = y + rr * 4;
        const int h  = h0 + yy;
        const float* wbase = weights + (long)bc * (RR * RR) * HW + h * WW + w0;

        float4 acc = make_float4(0.f, 0.f, 0.f, 0.f);

        #pragma unroll
        for (int i = 0; i < RR; i++) {
            // Batch: 7 weight vectors for this window row, streaming loads.
            float4 wv[RR];
            #pragma unroll
            for (int j = 0; j < RR; j++)
                wv[j] = __ldcs((const float4*)(wbase + (long)(i * RR + j) * HW));

            // 12 consecutive latent values covering cols w0-3 .. w0+8
            const float4* srow = (const float4*)&tile[yy + i][w0];
            float4 a = srow[0];
            float4 b = srow[1];
            float4 c = srow[2];
            float r[12] = { a.x, a.y, a.z, a.w,
                            b.x, b.y, b.z, b.w,
                            c.x, c.y, c.z, c.w };

            #pragma unroll
            for (int j = 0; j < RR; j++) {
                acc.x += wv[j].x * r[1 + j];
                acc.y += wv[j].y * r[2 + j];
                acc.z += wv[j].z * r[3 + j];
                acc.w += wv[j].w * r[4 + j];
            }
        }

        __stcs((float4*)(out + (long)bc * HW + h * WW + w0), acc);
    }
}

extern "C" void kernel_launch(void* const* d_in, const int* in_sizes, int n_in,
                              void* d_out, int out_size)
{
    const float* latent  = (const float*)d_in[0];
    const float* weights = (const float*)d_in[1];
    // d_in[2] = window_size (int scalar, always 7 here)
    float* out = (float*)d_out;

    dim3 block(64, 4, 1);
    dim3 grid(1, HH / TILE_ROWS, BB * CC);
    texdiff_kernel<<<grid, block>>>(latent, weights, out);
}

// round 5
// speedup vs baseline: 1.3672x; 1.3672x over previous
#include <cuda_runtime.h>

// BaseTextureDiffusion: out[b,c,h,w] = sum_{k=0..48} weights[b,c,k,h,w] *
//                       latent_edgepadded[b,c, h+k/7-3, w+k%7-3]
// Shapes: latent (2,24,256,256) f32, weights (2,24,49,256,256) f32, R=7.
//
// HBM-bound on the 616MB read-once weights stream. R5 = R2 skeleton
// (4-row tiles, 3072 blocks, __ldcs weights / __stcs out) + one-row
// software pipeline on the weights stream: double-buffered wv[2][7],
// row i+1's loads issue before row i's FMAs, so consumption never waits
// on freshly-issued loads. Occupancy capped at 3 to hold ~56 weight regs.

#define BB 2
#define CC 24
#define HH 256
#define WW 256
#define RR 7
#define PAD 3
#define HW (HH * WW)

#define TILE_ROWS 4                   // output rows per block
#define SROWS (TILE_ROWS + 2 * PAD)   // 10
#define SCOLS 264                     // latent cols -4..259

__global__ __launch_bounds__(256, 3)
void texdiff_kernel(const float* __restrict__ latent,
                    const float* __restrict__ weights,
                    float* __restrict__ out)
{
    __shared__ float tile[SROWS][SCOLS];

    const int bc = blockIdx.z;                 // 0..47  (b*C + c)
    const int h0 = blockIdx.y * TILE_ROWS;     // first output row of tile
    const int x  = threadIdx.x;                // 0..63 : float4 lane over w
    const int y  = threadIdx.y;                // 0..3  : row within tile
    const int tid = y * 64 + x;                // 0..255
    const int w0  = 4 * x;

    const float* lat = latent + (long)bc * HW;

    // Stage latent tile with edge clamp:
    // tile[r][cix] = latent[clamp(h0 + r - 3), clamp(cix - 4)]
    #pragma unroll
    for (int idx = tid; idx < SROWS * SCOLS; idx += 256) {
        int r   = idx / SCOLS;
        int cix = idx - r * SCOLS;
        int gh  = h0 + r - PAD;
        gh = gh < 0 ? 0 : (gh > HH - 1 ? HH - 1 : gh);
        int gw  = cix - 4;
        gw = gw < 0 ? 0 : (gw > WW - 1 ? WW - 1 : gw);
        tile[r][cix] = lat[gh * WW + gw];
    }
    __syncthreads();

    const int h = h0 + y;
    const float* wbase = weights + (long)bc * (RR * RR) * HW + h * WW + w0;

    float4 acc = make_float4(0.f, 0.f, 0.f, 0.f);

    // Double-buffered weights pipeline: load row 0, then each iteration
    // issues row i+1's loads before consuming row i.
    float4 wv[2][RR];
    #pragma unroll
    for (int j = 0; j < RR; j++)
        wv[0][j] = __ldcs((const float4*)(wbase + (long)j * HW));

    #pragma unroll
    for (int i = 0; i < RR; i++) {
        const int cur = i & 1;
        if (i < RR - 1) {
            #pragma unroll
            for (int j = 0; j < RR; j++)
                wv[cur ^ 1][j] =
                    __ldcs((const float4*)(wbase + (long)((i + 1) * RR + j) * HW));
        }

        // 12 consecutive latent values covering cols w0-3 .. w0+8
        const float4* srow = (const float4*)&tile[y + i][w0];
        float4 a = srow[0];
        float4 b = srow[1];
        float4 c = srow[2];
        float r[12] = { a.x, a.y, a.z, a.w,
                        b.x, b.y, b.z, b.w,
                        c.x, c.y, c.z, c.w };

        #pragma unroll
        for (int j = 0; j < RR; j++) {
            acc.x += wv[cur][j].x * r[1 + j];
            acc.y += wv[cur][j].y * r[2 + j];
            acc.z += wv[cur][j].z * r[3 + j];
            acc.w += wv[cur][j].w * r[4 + j];
        }
    }

    __stcs((float4*)(out + (long)bc * HW + h * WW + w0), acc);
}

extern "C" void kernel_launch(void* const* d_in, const int* in_sizes, int n_in,
                              void* d_out, int out_size)
{
    const float* latent  = (const float*)d_in[0];
    const float* weights = (const float*)d_in[1];
    // d_in[2] = window_size (int scalar, always 7 here)
    float* out = (float*)d_out;

    dim3 block(64, TILE_ROWS, 1);
    dim3 grid(1, HH / TILE_ROWS, BB * CC);
    texdiff_kernel<<<grid, block>>>(latent, weights, out);
}

// round 6
// speedup vs baseline: 1.3728x; 1.0041x over previous
#include <cuda_runtime.h>

// BaseTextureDiffusion: out[b,c,h,w] = sum_{k=0..48} weights[b,c,k,h,w] *
//                       latent_edgepadded[b,c, h+k/7-3, w+k%7-3]
// Shapes: latent (2,24,256,256) f32, weights (2,24,49,256,256) f32, R=7.
//
// HBM-bound on the 616MB read-once weights stream. R6 = R5 (94.7us:
// double-buffered 7-vector weights pipeline, occ-3) + hoist the row-0
// weight loads ABOVE the latent tile staging + __syncthreads, so the
// block-startup stall on weights overlaps the smem staging instead of
// serializing after it.

#define BB 2
#define CC 24
#define HH 256
#define WW 256
#define RR 7
#define PAD 3
#define HW (HH * WW)

#define TILE_ROWS 4                   // output rows per block
#define SROWS (TILE_ROWS + 2 * PAD)   // 10
#define SCOLS 264                     // latent cols -4..259

__global__ __launch_bounds__(256, 3)
void texdiff_kernel(const float* __restrict__ latent,
                    const float* __restrict__ weights,
                    float* __restrict__ out)
{
    __shared__ float tile[SROWS][SCOLS];

    const int bc = blockIdx.z;                 // 0..47  (b*C + c)
    const int h0 = blockIdx.y * TILE_ROWS;     // first output row of tile
    const int x  = threadIdx.x;                // 0..63 : float4 lane over w
    const int y  = threadIdx.y;                // 0..3  : row within tile
    const int tid = y * 64 + x;                // 0..255
    const int w0  = 4 * x;

    const int h = h0 + y;
    const float* wbase = weights + (long)bc * (RR * RR) * HW + h * WW + w0;

    // Issue row-0 weight loads FIRST — independent of smem, so their
    // latency overlaps the tile staging below instead of following it.
    float4 wv[2][RR];
    #pragma unroll
    for (int j = 0; j < RR; j++)
        wv[0][j] = __ldcs((const float4*)(wbase + (long)j * HW));

    const float* lat = latent + (long)bc * HW;

    // Stage latent tile with edge clamp:
    // tile[r][cix] = latent[clamp(h0 + r - 3), clamp(cix - 4)]
    #pragma unroll
    for (int idx = tid; idx < SROWS * SCOLS; idx += 256) {
        int r   = idx / SCOLS;
        int cix = idx - r * SCOLS;
        int gh  = h0 + r - PAD;
        gh = gh < 0 ? 0 : (gh > HH - 1 ? HH - 1 : gh);
        int gw  = cix - 4;
        gw = gw < 0 ? 0 : (gw > WW - 1 ? WW - 1 : gw);
        tile[r][cix] = lat[gh * WW + gw];
    }
    __syncthreads();

    float4 acc = make_float4(0.f, 0.f, 0.f, 0.f);

    #pragma unroll
    for (int i = 0; i < RR; i++) {
        const int cur = i & 1;
        if (i < RR - 1) {
            #pragma unroll
            for (int j = 0; j < RR; j++)
                wv[cur ^ 1][j] =
                    __ldcs((const float4*)(wbase + (long)((i + 1) * RR + j) * HW));
        }

        // 12 consecutive latent values covering cols w0-3 .. w0+8
        const float4* srow = (const float4*)&tile[y + i][w0];
        float4 a = srow[0];
        float4 b = srow[1];
        float4 c = srow[2];
        float r[12] = { a.x, a.y, a.z, a.w,
                        b.x, b.y, b.z, b.w,
                        c.x, c.y, c.z, c.w };

        #pragma unroll
        for (int j = 0; j < RR; j++) {
            acc.x += wv[cur][j].x * r[1 + j];
            acc.y += wv[cur][j].y * r[2 + j];
            acc.z += wv[cur][j].z * r[3 + j];
            acc.w += wv[cur][j].w * r[4 + j];
        }
    }

    __stcs((float4*)(out + (long)bc * HW + h * WW + w0), acc);
}

extern "C" void kernel_launch(void* const* d_in, const int* in_sizes, int n_in,
                              void* d_out, int out_size)
{
    const float* latent  = (const float*)d_in[0];
    const float* weights = (const float*)d_in[1];
    // d_in[2] = window_size (int scalar, always 7 here)
    float* out = (float*)d_out;

    dim3 block(64, TILE_ROWS, 1);
    dim3 grid(1, HH / TILE_ROWS, BB * CC);
    texdiff_kernel<<<grid, block>>>(latent, weights, out);
}

// round 7
// speedup vs baseline: 1.4316x; 1.0428x over previous
#include <cuda_runtime.h>

// BaseTextureDiffusion: out[b,c,h,w] = sum_{k=0..48} weights[b,c,k,h,w] *
//                       latent_edgepadded[b,c, h+k/7-3, w+k%7-3]
// Shapes: latent (2,24,256,256) f32, weights (2,24,49,256,256) f32, R=7.
//
// HBM-bound on the 616MB read-once weights stream. R7 = R6 (94.3us:
// double-buffered 7-vector weights pipeline, row-0 loads hoisted above
// staging, occ-3) + VECTORIZED latent staging: interior tile columns are
// aligned float4 copies (660 LDG.128/block instead of 2640 scalar LDG),
// only the 4-wide left/right aprons take clamped scalar splats. Frees LSU
// issue slots + L1tex wavefront entries for the weight stream.

#define BB 2
#define CC 24
#define HH 256
#define WW 256
#define RR 7
#define PAD 3
#define HW (HH * WW)

#define TILE_ROWS 4                   // output rows per block
#define SROWS (TILE_ROWS + 2 * PAD)   // 10
#define SCOLS 264                     // latent cols -4..259
#define SC4   (SCOLS / 4)             // 66 float4 slots per tile row

__global__ __launch_bounds__(256, 3)
void texdiff_kernel(const float* __restrict__ latent,
                    const float* __restrict__ weights,
                    float* __restrict__ out)
{
    __shared__ float tile[SROWS][SCOLS];

    const int bc = blockIdx.z;                 // 0..47  (b*C + c)
    const int h0 = blockIdx.y * TILE_ROWS;     // first output row of tile
    const int x  = threadIdx.x;                // 0..63 : float4 lane over w
    const int y  = threadIdx.y;                // 0..3  : row within tile
    const int tid = y * 64 + x;                // 0..255
    const int w0  = 4 * x;

    const int h = h0 + y;
    const float* wbase = weights + (long)bc * (RR * RR) * HW + h * WW + w0;

    // Issue row-0 weight loads FIRST — independent of smem, so their
    // latency overlaps the tile staging below instead of following it.
    float4 wv[2][RR];
    #pragma unroll
    for (int j = 0; j < RR; j++)
        wv[0][j] = __ldcs((const float4*)(wbase + (long)j * HW));

    const float* lat = latent + (long)bc * HW;

    // Stage latent tile with edge clamp, vectorized:
    // tile[r][c4*4 + t] = latent[clamp(h0 + r - 3), clamp(c4*4 + t - 4)]
    // Interior slots c4=1..64 are aligned float4 copies; c4=0 / c4=65 are
    // clamped scalar splats of column 0 / 255.
    #pragma unroll
    for (int idx = tid; idx < SROWS * SC4; idx += 256) {
        int r  = idx / SC4;
        int c4 = idx - r * SC4;
        int gh = h0 + r - PAD;
        gh = gh < 0 ? 0 : (gh > HH - 1 ? HH - 1 : gh);
        const float* lrow = lat + gh * WW;
        float4* dst = (float4*)&tile[r][c4 * 4];
        if (c4 == 0) {
            float v = lrow[0];
            *dst = make_float4(v, v, v, v);
        } else if (c4 == SC4 - 1) {
            float v = lrow[WW - 1];
            *dst = make_float4(v, v, v, v);
        } else {
            *dst = *(const float4*)(lrow + (c4 - 1) * 4);
        }
    }
    __syncthreads();

    float4 acc = make_float4(0.f, 0.f, 0.f, 0.f);

    #pragma unroll
    for (int i = 0; i < RR; i++) {
        const int cur = i & 1;
        if (i < RR - 1) {
            #pragma unroll
            for (int j = 0; j < RR; j++)
                wv[cur ^ 1][j] =
                    __ldcs((const float4*)(wbase + (long)((i + 1) * RR + j) * HW));
        }

        // 12 consecutive latent values covering cols w0-3 .. w0+8
        const float4* srow = (const float4*)&tile[y + i][w0];
        float4 a = srow[0];
        float4 b = srow[1];
        float4 c = srow[2];
        float r[12] = { a.x, a.y, a.z, a.w,
                        b.x, b.y, b.z, b.w,
                        c.x, c.y, c.z, c.w };

        #pragma unroll
        for (int j = 0; j < RR; j++) {
            acc.x += wv[cur][j].x * r[1 + j];
            acc.y += wv[cur][j].y * r[2 + j];
            acc.z += wv[cur][j].z * r[3 + j];
            acc.w += wv[cur][j].w * r[4 + j];
        }
    }

    __stcs((float4*)(out + (long)bc * HW + h * WW + w0), acc);
}

extern "C" void kernel_launch(void* const* d_in, const int* in_sizes, int n_in,
                              void* d_out, int out_size)
{
    const float* latent  = (const float*)d_in[0];
    const float* weights = (const float*)d_in[1];
    // d_in[2] = window_size (int scalar, always 7 here)
    float* out = (float*)d_out;

    dim3 block(64, TILE_ROWS, 1);
    dim3 grid(1, HH / TILE_ROWS, BB * CC);
    texdiff_kernel<<<grid, block>>>(latent, weights, out);
}